// round 4
// baseline (speedup 1.0000x reference)
#include <cuda_runtime.h>
#include <math.h>

#define Bk 64
#define Sk 1024
#define Ck 512
#define Vk 140
#define Ak 512
#define Hk 512
#define Tk 128
#define GATES 2048   // 4*H
#define INW 652      // V + A

// ---------------- device state (static allocation only) ----------------
__device__ float g_keys[(size_t)Bk * Sk * Ak];   // 134 MB
__device__ float g_h[Bk * Hk];
__device__ float g_c[Bk * Hk];
__device__ float g_q[Bk * Ak];
__device__ float g_ctx[Bk * Ak];
__device__ float g_gates[Bk * GATES];
__device__ float g_pm[1024];
__device__ float g_pl[1024];
__device__ float g_pctx[1024 * Ak];
__device__ int   g_idx[Bk];

__device__ __forceinline__ float sigmf(float x) { return 1.f / (1.f + expf(-x)); }

// ---------------- init: h=c=0, q = Hc_b (since h0 = 0), idx = labels[:,0] ----
__global__ void init_kernel(const int* __restrict__ labels,
                            const float* __restrict__ Hc_b) {
    int b = blockIdx.x, tid = threadIdx.x;
    g_h[b * Hk + tid] = 0.f;
    g_c[b * Hk + tid] = 0.f;
    g_q[b * Ak + tid] = Hc_b[tid];
    if (tid == 0) g_idx[b] = labels[b * Tk];
}

// ---------------- keys = X @ Ic_w^T + Ic_b  (once) ----------------------
// grid (1024, 8), block 256. 64x64 output tile, 4x4 per thread, K-tile 32.
__global__ void keys_gemm(const float* __restrict__ X,
                          const float* __restrict__ W,
                          const float* __restrict__ bias) {
    const int bs0 = blockIdx.x * 64;
    const int a0  = blockIdx.y * 64;
    const int tid = threadIdx.x;
    const int tx = tid & 15, ty = tid >> 4;
    __shared__ float Xs[64][33];
    __shared__ float Ws[64][33];
    float acc[4][4] = {};
    for (int k0 = 0; k0 < Ck; k0 += 32) {
        for (int idx = tid; idx < 64 * 32; idx += 256) {
            int r = idx >> 5, kk = idx & 31;
            Xs[r][kk] = X[(size_t)(bs0 + r) * Ck + k0 + kk];
            Ws[r][kk] = W[(size_t)(a0 + r) * Ck + k0 + kk];
        }
        __syncthreads();
#pragma unroll
        for (int kk = 0; kk < 32; kk++) {
            float xr[4], wc[4];
#pragma unroll
            for (int i = 0; i < 4; i++) xr[i] = Xs[ty * 4 + i][kk];
#pragma unroll
            for (int j = 0; j < 4; j++) wc[j] = Ws[tx * 4 + j][kk];
#pragma unroll
            for (int i = 0; i < 4; i++)
#pragma unroll
                for (int j = 0; j < 4; j++) acc[i][j] += xr[i] * wc[j];
        }
        __syncthreads();
    }
#pragma unroll
    for (int i = 0; i < 4; i++)
#pragma unroll
        for (int j = 0; j < 4; j++)
            g_keys[(size_t)(bs0 + ty * 4 + i) * Ak + a0 + tx * 4 + j] =
                acc[i][j] + bias[a0 + tx * 4 + j];
}

// ---------------- attention: one-pass online softmax over S chunk -------
// grid 1024 (64 b x 16 chunks of 64 s), block 256 (8 warps, 8 s per warp).
// Each lane owns a-positions {j*128 + lane*4 + c : j<4, c<4} (16 floats).
__global__ void attn_kernel() {
    const int bx = blockIdx.x;
    const int b = bx >> 4;
    const int chunk = bx & 15;
    const int tid = threadIdx.x;
    const int lane = tid & 31;
    const int w = tid >> 5;

    __shared__ __align__(16) float q_s[Ak];
    __shared__ float ctx_s[Ak];
    __shared__ float red_m[8], red_l[8];

    q_s[tid]       = g_q[b * Ak + tid];
    q_s[tid + 256] = g_q[b * Ak + tid + 256];
    ctx_s[tid] = 0.f;
    ctx_s[tid + 256] = 0.f;
    __syncthreads();

    const float4* q4 = (const float4*)q_s;
    const float4 qv0 = q4[lane], qv1 = q4[32 + lane],
                 qv2 = q4[64 + lane], qv3 = q4[96 + lane];

    float m = -1e30f, l = 0.f;
    float4 a0 = make_float4(0, 0, 0, 0), a1 = a0, a2 = a0, a3 = a0;
    const float* kb = g_keys + ((size_t)b * Sk + chunk * 64) * Ak;

    for (int i = 0; i < 8; i++) {
        const float4* row = (const float4*)(kb + (size_t)(i * 8 + w) * Ak);
        float4 k0 = row[lane], k1 = row[32 + lane],
               k2 = row[64 + lane], k3 = row[96 + lane];
        float d = k0.x * qv0.x + k0.y * qv0.y + k0.z * qv0.z + k0.w * qv0.w
                + k1.x * qv1.x + k1.y * qv1.y + k1.z * qv1.z + k1.w * qv1.w
                + k2.x * qv2.x + k2.y * qv2.y + k2.z * qv2.z + k2.w * qv2.w
                + k3.x * qv3.x + k3.y * qv3.y + k3.z * qv3.z + k3.w * qv3.w;
#pragma unroll
        for (int o = 16; o; o >>= 1) d += __shfl_xor_sync(0xffffffffu, d, o);
        float score = d * 0.04419417382415922f;  // 1/sqrt(512)
        float nm = fmaxf(m, score);
        float corr = expf(m - nm);
        float p = expf(score - nm);
        l = l * corr + p;
        a0.x = a0.x * corr + p * k0.x; a0.y = a0.y * corr + p * k0.y;
        a0.z = a0.z * corr + p * k0.z; a0.w = a0.w * corr + p * k0.w;
        a1.x = a1.x * corr + p * k1.x; a1.y = a1.y * corr + p * k1.y;
        a1.z = a1.z * corr + p * k1.z; a1.w = a1.w * corr + p * k1.w;
        a2.x = a2.x * corr + p * k2.x; a2.y = a2.y * corr + p * k2.y;
        a2.z = a2.z * corr + p * k2.z; a2.w = a2.w * corr + p * k2.w;
        a3.x = a3.x * corr + p * k3.x; a3.y = a3.y * corr + p * k3.y;
        a3.z = a3.z * corr + p * k3.z; a3.w = a3.w * corr + p * k3.w;
        m = nm;
    }
    if (lane == 0) { red_m[w] = m; red_l[w] = l; }
    __syncthreads();
    float M = red_m[0];
#pragma unroll
    for (int i = 1; i < 8; i++) M = fmaxf(M, red_m[i]);
    float Lb = 0.f;
#pragma unroll
    for (int i = 0; i < 8; i++) Lb += red_l[i] * expf(red_m[i] - M);
    float f = expf(m - M);  // m,l identical across lanes of this warp
    atomicAdd(&ctx_s[0 * 128 + lane * 4 + 0], f * a0.x);
    atomicAdd(&ctx_s[0 * 128 + lane * 4 + 1], f * a0.y);
    atomicAdd(&ctx_s[0 * 128 + lane * 4 + 2], f * a0.z);
    atomicAdd(&ctx_s[0 * 128 + lane * 4 + 3], f * a0.w);
    atomicAdd(&ctx_s[1 * 128 + lane * 4 + 0], f * a1.x);
    atomicAdd(&ctx_s[1 * 128 + lane * 4 + 1], f * a1.y);
    atomicAdd(&ctx_s[1 * 128 + lane * 4 + 2], f * a1.z);
    atomicAdd(&ctx_s[1 * 128 + lane * 4 + 3], f * a1.w);
    atomicAdd(&ctx_s[2 * 128 + lane * 4 + 0], f * a2.x);
    atomicAdd(&ctx_s[2 * 128 + lane * 4 + 1], f * a2.y);
    atomicAdd(&ctx_s[2 * 128 + lane * 4 + 2], f * a2.z);
    atomicAdd(&ctx_s[2 * 128 + lane * 4 + 3], f * a2.w);
    atomicAdd(&ctx_s[3 * 128 + lane * 4 + 0], f * a3.x);
    atomicAdd(&ctx_s[3 * 128 + lane * 4 + 1], f * a3.y);
    atomicAdd(&ctx_s[3 * 128 + lane * 4 + 2], f * a3.z);
    atomicAdd(&ctx_s[3 * 128 + lane * 4 + 3], f * a3.w);
    __syncthreads();
    if (tid == 0) { g_pm[bx] = M; g_pl[bx] = Lb; }
    g_pctx[bx * Ak + tid]       = ctx_s[tid];
    g_pctx[bx * Ak + tid + 256] = ctx_s[tid + 256];
}

// ---------------- merge 16 partials per batch -> ctx --------------------
__global__ void merge_kernel() {
    const int b = blockIdx.x, tid = threadIdx.x;
    __shared__ float pm[16], pl[16];
    if (tid < 16) { pm[tid] = g_pm[b * 16 + tid]; pl[tid] = g_pl[b * 16 + tid]; }
    __syncthreads();
    float M = pm[0];
#pragma unroll
    for (int i = 1; i < 16; i++) M = fmaxf(M, pm[i]);
    float fac[16];
    float L = 0.f;
#pragma unroll
    for (int i = 0; i < 16; i++) { fac[i] = expf(pm[i] - M); L += pl[i] * fac[i]; }
    float invL = 1.f / L;
#pragma unroll
    for (int r = 0; r < 2; r++) {
        int a = tid + r * 256;
        float s = 0.f;
#pragma unroll
        for (int i = 0; i < 16; i++)
            s += fac[i] * g_pctx[(size_t)(b * 16 + i) * Ak + a];
        g_ctx[b * Ak + a] = s * invL;
    }
}

// ---------------- gates = W_ih[:,V:]@ctx + W_hh@h + biases + onehot col --
// grid 64 (16 row-tiles x 4 b-tiles), block 256.
__global__ void gates_kernel(const float* __restrict__ W_ih,
                             const float* __restrict__ b_ih,
                             const float* __restrict__ W_hh,
                             const float* __restrict__ b_hh) {
    const int rowTile = blockIdx.x >> 2;
    const int bTile = blockIdx.x & 3;
    const int tid = threadIdx.x;
    const int rl = tid & 127;
    const int bg = tid >> 7;
    __shared__ float Wt[128][33];
    __shared__ float Xt[16][33];
    float acc[8] = {};
    const int row0 = rowTile * 128;
    const int bb0 = bTile * 16;
    for (int k0 = 0; k0 < 1024; k0 += 32) {
        for (int idx = tid; idx < 128 * 32; idx += 256) {
            int r = idx >> 5, kk = idx & 31;
            int kg = k0 + kk;
            int row = row0 + r;
            Wt[r][kk] = (kg < 512) ? W_ih[(size_t)row * INW + Vk + kg]
                                   : W_hh[(size_t)row * Hk + kg - 512];
        }
        for (int idx = tid; idx < 16 * 32; idx += 256) {
            int r = idx >> 5, kk = idx & 31;
            int kg = k0 + kk;
            int bb = bb0 + r;
            Xt[r][kk] = (kg < 512) ? g_ctx[bb * Ak + kg]
                                   : g_h[bb * Hk + kg - 512];
        }
        __syncthreads();
#pragma unroll
        for (int kk = 0; kk < 32; kk++) {
            float wv = Wt[rl][kk];
#pragma unroll
            for (int j = 0; j < 8; j++) acc[j] += wv * Xt[bg * 8 + j][kk];
        }
        __syncthreads();
    }
    const int row = row0 + rl;
    const float base = b_ih[row] + b_hh[row];
#pragma unroll
    for (int j = 0; j < 8; j++) {
        int bb = bb0 + bg * 8 + j;
        g_gates[bb * GATES + row] =
            acc[j] + base + W_ih[(size_t)row * INW + g_idx[bb]];
    }
}

// ---------------- LSTM pointwise + logits + argmax ----------------------
// grid 64 (one block per batch), block 256.
__global__ void finish_kernel(const float* __restrict__ Wout,
                              const float* __restrict__ b_out,
                              float* __restrict__ out, int t) {
    const int b = blockIdx.x, tid = threadIdx.x;
    const int lane = tid & 31, w = tid >> 5;
    __shared__ __align__(16) float h_s[Hk];
    __shared__ float logit_s[Vk];
#pragma unroll
    for (int r = 0; r < 2; r++) {
        int jj = tid + r * 256;
        float gi = g_gates[b * GATES + jj];
        float gf = g_gates[b * GATES + 512 + jj];
        float gg = g_gates[b * GATES + 1024 + jj];
        float go = g_gates[b * GATES + 1536 + jj];
        float cprev = g_c[b * Hk + jj];
        float cn = sigmf(gf) * cprev + sigmf(gi) * tanhf(gg);
        float hn = sigmf(go) * tanhf(cn);
        g_c[b * Hk + jj] = cn;
        g_h[b * Hk + jj] = hn;
        h_s[jj] = hn;
    }
    __syncthreads();
    const float4* h4 = (const float4*)h_s;
    for (int v = w; v < Vk; v += 8) {
        const float4* wr = (const float4*)(Wout + (size_t)v * Hk);
        float s = 0.f;
#pragma unroll
        for (int j = 0; j < 4; j++) {
            float4 a = wr[j * 32 + lane];
            float4 hv = h4[j * 32 + lane];
            s += a.x * hv.x + a.y * hv.y + a.z * hv.z + a.w * hv.w;
        }
#pragma unroll
        for (int o = 16; o; o >>= 1) s += __shfl_xor_sync(0xffffffffu, s, o);
        if (lane == 0) {
            float lv = s + b_out[v];
            logit_s[v] = lv;
            out[((size_t)b * Tk + t) * Vk + v] = lv;
        }
    }
    __syncthreads();
    if (tid == 0) {
        float best = logit_s[0];
        int bi = 0;
        for (int v = 1; v < Vk; v++) {
            float lv = logit_s[v];
            if (lv > best) { best = lv; bi = v; }
        }
        g_idx[b] = bi;
    }
}

// ---------------- q = h_new @ Hc_w^T + Hc_b -----------------------------
// grid 16 (4 row-tiles x 4 b-tiles), block 256.
__global__ void qproj_kernel(const float* __restrict__ Hc_w,
                             const float* __restrict__ Hc_b) {
    const int rowTile = blockIdx.x >> 2;
    const int bTile = blockIdx.x & 3;
    const int tid = threadIdx.x;
    const int rl = tid & 127;
    const int bg = tid >> 7;
    __shared__ float Wt[128][33];
    __shared__ float Xt[16][33];
    float acc[8] = {};
    const int row0 = rowTile * 128;
    const int bb0 = bTile * 16;
    for (int k0 = 0; k0 < 512; k0 += 32) {
        for (int idx = tid; idx < 128 * 32; idx += 256) {
            int r = idx >> 5, kk = idx & 31;
            Wt[r][kk] = Hc_w[(size_t)(row0 + r) * Hk + k0 + kk];
        }
        for (int idx = tid; idx < 16 * 32; idx += 256) {
            int r = idx >> 5, kk = idx & 31;
            Xt[r][kk] = g_h[(bb0 + r) * Hk + k0 + kk];
        }
        __syncthreads();
#pragma unroll
        for (int kk = 0; kk < 32; kk++) {
            float wv = Wt[rl][kk];
#pragma unroll
            for (int j = 0; j < 8; j++) acc[j] += wv * Xt[bg * 8 + j][kk];
        }
        __syncthreads();
    }
    const int row = row0 + rl;
    const float bias = Hc_b[row];
#pragma unroll
    for (int j = 0; j < 8; j++) {
        int bb = bb0 + bg * 8 + j;
        g_q[bb * Ak + row] = acc[j] + bias;
    }
}

// ---------------- launch ------------------------------------------------
extern "C" void kernel_launch(void* const* d_in, const int* in_sizes, int n_in,
                              void* d_out, int out_size) {
    const float* image  = (const float*)d_in[0];
    const int*   labels = (const int*)d_in[1];
    const float* Ic_w   = (const float*)d_in[2];
    const float* Ic_b   = (const float*)d_in[3];
    const float* Hc_w   = (const float*)d_in[4];
    const float* Hc_b   = (const float*)d_in[5];
    const float* W_ih   = (const float*)d_in[6];
    const float* b_ih   = (const float*)d_in[7];
    const float* W_hh   = (const float*)d_in[8];
    const float* b_hh   = (const float*)d_in[9];
    const float* Wout   = (const float*)d_in[10];
    const float* b_out  = (const float*)d_in[11];
    float* out = (float*)d_out;

    init_kernel<<<Bk, 512>>>(labels, Hc_b);
    keys_gemm<<<dim3((Bk * Sk) / 64, Ak / 64), 256>>>(image, Ic_w, Ic_b);

    for (int t = 0; t < Tk; t++) {
        attn_kernel<<<1024, 256>>>();
        merge_kernel<<<Bk, 256>>>();
        gates_kernel<<<64, 256>>>(W_ih, b_ih, W_hh, b_hh);
        finish_kernel<<<Bk, 256>>>(Wout, b_out, out, t);
        if (t + 1 < Tk) qproj_kernel<<<16, 256>>>(Hc_w, Hc_b);
    }
}

// round 5
// speedup vs baseline: 1.3445x; 1.3445x over previous
#include <cuda_runtime.h>
#include <math.h>

#define Bk 64
#define Sk 1024
#define Ck 512
#define Vk 140
#define Ak 512
#define Hk 512
#define Tk 128
#define GATES 2048   // 4*H
#define INW 652      // V + A
#define NCHUNK 32    // S chunks per batch (32 rows each)

// ---------------- device state (static allocation only) ----------------
__device__ float g_keys[(size_t)Bk * Sk * Ak];     // 134 MB
__device__ float g_h[Bk * Hk];
__device__ float g_c[Bk * Hk];
__device__ float g_q[Bk * Ak];
__device__ float g_ctx[Bk * Ak];
__device__ float g_gA[Bk * GATES];
__device__ float g_gB[Bk * GATES];
__device__ float g_pm[Bk * NCHUNK];
__device__ float g_pl[Bk * NCHUNK];
__device__ float g_pctx[(size_t)Bk * NCHUNK * Ak]; // 4 MB
__device__ int   g_cnt[Bk];
__device__ int   g_idx[Bk];

__device__ __forceinline__ float sigmf(float x) { return 1.f / (1.f + expf(-x)); }

// ---------------- init ---------------------------------------------------
__global__ void init_kernel(const int* __restrict__ labels,
                            const float* __restrict__ Hc_b) {
    int b = blockIdx.x, tid = threadIdx.x;
    g_h[b * Hk + tid] = 0.f;
    g_c[b * Hk + tid] = 0.f;
    g_q[b * Ak + tid] = Hc_b[tid];
    if (tid == 0) { g_idx[b] = labels[b * Tk]; g_cnt[b] = 0; }
}

// ---------------- keys = X @ Ic_w^T + Ic_b  (once) ------------------------
__global__ void keys_gemm(const float* __restrict__ X,
                          const float* __restrict__ W,
                          const float* __restrict__ bias) {
    const int bs0 = blockIdx.x * 64;
    const int a0  = blockIdx.y * 64;
    const int tid = threadIdx.x;
    const int tx = tid & 15, ty = tid >> 4;
    __shared__ float Xs[64][33];
    __shared__ float Ws[64][33];
    float acc[4][4] = {};
    for (int k0 = 0; k0 < Ck; k0 += 32) {
        for (int idx = tid; idx < 64 * 32; idx += 256) {
            int r = idx >> 5, kk = idx & 31;
            Xs[r][kk] = X[(size_t)(bs0 + r) * Ck + k0 + kk];
            Ws[r][kk] = W[(size_t)(a0 + r) * Ck + k0 + kk];
        }
        __syncthreads();
#pragma unroll
        for (int kk = 0; kk < 32; kk++) {
            float xr[4], wc[4];
#pragma unroll
            for (int i = 0; i < 4; i++) xr[i] = Xs[ty * 4 + i][kk];
#pragma unroll
            for (int j = 0; j < 4; j++) wc[j] = Ws[tx * 4 + j][kk];
#pragma unroll
            for (int i = 0; i < 4; i++)
#pragma unroll
                for (int j = 0; j < 4; j++) acc[i][j] += xr[i] * wc[j];
        }
        __syncthreads();
    }
#pragma unroll
    for (int i = 0; i < 4; i++)
#pragma unroll
        for (int j = 0; j < 4; j++)
            g_keys[(size_t)(bs0 + ty * 4 + i) * Ak + a0 + tx * 4 + j] =
                acc[i][j] + bias[a0 + tx * 4 + j];
}

// ---------------- attention: two-pass block softmax + fused merge --------
// grid 2048 (64 b x 32 chunks of 32 s), block 256 (8 warps, 4 rows/warp).
// Dynamic smem: keys tile 64 KB + q 2KB + ctx 2KB + scores/facs/misc.
#define SMEM_ATTN_FLOATS (16384 + 512 + 512 + 32 + 32 + 8)
__global__ void attn_kernel() {
    extern __shared__ float sm[];
    float* keys_s = sm;                 // [32][512]
    float* q_s    = sm + 16384;         // [512]
    float* ctx_s  = sm + 16896;         // [512]
    float* scores = sm + 17408;         // [32]
    float* facs   = sm + 17440;         // [32]
    float* lg_s   = sm + 17472;         // [1]
    int*   flag   = (int*)(sm + 17473); // [1]

    const int bx = blockIdx.x;
    const int b = bx >> 5;
    const int chunk = bx & 31;
    const int tid = threadIdx.x;
    const int lane = tid & 31;
    const int w = tid >> 5;

    q_s[tid]       = g_q[b * Ak + tid];
    q_s[tid + 256] = g_q[b * Ak + tid + 256];
    ctx_s[tid] = 0.f;
    ctx_s[tid + 256] = 0.f;
    __syncthreads();

    const float4* q4 = (const float4*)q_s;
    const float4 qv0 = q4[lane], qv1 = q4[32 + lane],
                 qv2 = q4[64 + lane], qv3 = q4[96 + lane];

    // ---- Pass A: load rows to smem, compute raw scores (no carried deps)
    const float* kb = g_keys + ((size_t)b * Sk + chunk * 32) * Ak;
#pragma unroll
    for (int i = 0; i < 4; i++) {
        const int row = w * 4 + i;
        const float4* src = (const float4*)(kb + (size_t)row * Ak);
        float4 k0 = src[lane], k1 = src[32 + lane],
               k2 = src[64 + lane], k3 = src[96 + lane];
        float4* dst = (float4*)(keys_s + row * Ak);
        dst[lane] = k0; dst[32 + lane] = k1;
        dst[64 + lane] = k2; dst[96 + lane] = k3;
        float d = k0.x * qv0.x + k0.y * qv0.y + k0.z * qv0.z + k0.w * qv0.w
                + k1.x * qv1.x + k1.y * qv1.y + k1.z * qv1.z + k1.w * qv1.w
                + k2.x * qv2.x + k2.y * qv2.y + k2.z * qv2.z + k2.w * qv2.w
                + k3.x * qv3.x + k3.y * qv3.y + k3.z * qv3.z + k3.w * qv3.w;
#pragma unroll
        for (int o = 16; o; o >>= 1) d += __shfl_xor_sync(0xffffffffu, d, o);
        if (lane == 0) scores[row] = d * 0.04419417382415922f;  // 1/sqrt(512)
    }
    __syncthreads();

    // ---- Pass B: exact block softmax stats (redundant per warp, cheap)
    float s_l = scores[lane];
    float M = s_l;
#pragma unroll
    for (int o = 16; o; o >>= 1) M = fmaxf(M, __shfl_xor_sync(0xffffffffu, M, o));
    float p_l = expf(s_l - M);
    float L = p_l;
#pragma unroll
    for (int o = 16; o; o >>= 1) L += __shfl_xor_sync(0xffffffffu, L, o);

    // ---- Pass C: weighted sum from smem (no deps, no atomics)
    float4 a0 = make_float4(0, 0, 0, 0), a1 = a0, a2 = a0, a3 = a0;
#pragma unroll
    for (int i = 0; i < 4; i++) {
        const int row = w * 4 + i;
        const float p = __shfl_sync(0xffffffffu, p_l, row);
        const float4* kr = (const float4*)(keys_s + row * Ak);
        float4 k0 = kr[lane], k1 = kr[32 + lane],
               k2 = kr[64 + lane], k3 = kr[96 + lane];
        a0.x += p * k0.x; a0.y += p * k0.y; a0.z += p * k0.z; a0.w += p * k0.w;
        a1.x += p * k1.x; a1.y += p * k1.y; a1.z += p * k1.z; a1.w += p * k1.w;
        a2.x += p * k2.x; a2.y += p * k2.y; a2.z += p * k2.z; a2.w += p * k2.w;
        a3.x += p * k3.x; a3.y += p * k3.y; a3.z += p * k3.z; a3.w += p * k3.w;
    }

    // deterministic 8-round cross-warp accumulation into ctx_s
    for (int r = 0; r < 8; r++) {
        if (w == r) {
            float* c0 = ctx_s + lane * 4;
            c0[0]   += a0.x; c0[1]   += a0.y; c0[2]   += a0.z; c0[3]   += a0.w;
            c0[128] += a1.x; c0[129] += a1.y; c0[130] += a1.z; c0[131] += a1.w;
            c0[256] += a2.x; c0[257] += a2.y; c0[258] += a2.z; c0[259] += a2.w;
            c0[384] += a3.x; c0[385] += a3.y; c0[386] += a3.z; c0[387] += a3.w;
        }
        __syncthreads();
    }

    // write partials
    g_pctx[(size_t)bx * Ak + tid]       = ctx_s[tid];
    g_pctx[(size_t)bx * Ak + tid + 256] = ctx_s[tid + 256];
    if (tid == 0) { g_pm[bx] = M; g_pl[bx] = L; }

    // ---- fused merge: last block for this batch reduces all 32 partials
    __threadfence();
    if (tid == 0) {
        int prev = atomicAdd(&g_cnt[b], 1);
        flag[0] = (prev == NCHUNK - 1) ? 1 : 0;
    }
    __syncthreads();
    if (flag[0]) {
        __threadfence();
        if (w == 0) {
            float pm_l = __ldcg(&g_pm[b * NCHUNK + lane]);
            float pl_l = __ldcg(&g_pl[b * NCHUNK + lane]);
            float Mg = pm_l;
#pragma unroll
            for (int o = 16; o; o >>= 1)
                Mg = fmaxf(Mg, __shfl_xor_sync(0xffffffffu, Mg, o));
            float fl = expf(pm_l - Mg);
            float Ll = fl * pl_l;
#pragma unroll
            for (int o = 16; o; o >>= 1) Ll += __shfl_xor_sync(0xffffffffu, Ll, o);
            facs[lane] = fl;
            if (lane == 0) lg_s[0] = Ll;
        }
        __syncthreads();
        const float invL = 1.f / lg_s[0];
#pragma unroll
        for (int r2 = 0; r2 < 2; r2++) {
            int a = tid + r2 * 256;
            float s = 0.f;
#pragma unroll
            for (int c = 0; c < NCHUNK; c++)
                s += facs[c] * __ldcg(&g_pctx[(size_t)(b * NCHUNK + c) * Ak + a]);
            g_ctx[b * Ak + a] = s * invL;
        }
        if (tid == 0) g_cnt[b] = 0;
    }
}

// ---------------- gates, split-K x2 --------------------------------------
// grid 128 (16 rowTiles x 4 bTiles x 2 ksplits), block 256.
__global__ void gates_kernel(const float* __restrict__ W_ih,
                             const float* __restrict__ b_ih,
                             const float* __restrict__ W_hh,
                             const float* __restrict__ b_hh) {
    const int ks = blockIdx.x & 1;
    const int bTile = (blockIdx.x >> 1) & 3;
    const int rowTile = blockIdx.x >> 3;
    const int tid = threadIdx.x;
    const int rl = tid & 127;
    const int bg = tid >> 7;
    __shared__ float Wt[128][33];
    __shared__ float Xt[16][33];
    float acc[8] = {};
    const int row0 = rowTile * 128;
    const int bb0 = bTile * 16;
    const float* xsrc = ks ? g_h : g_ctx;
    for (int k0 = 0; k0 < 512; k0 += 32) {
        for (int idx = tid; idx < 128 * 32; idx += 256) {
            int r = idx >> 5, kk = idx & 31;
            int row = row0 + r;
            Wt[r][kk] = ks ? W_hh[(size_t)row * Hk + k0 + kk]
                           : W_ih[(size_t)row * INW + Vk + k0 + kk];
        }
        for (int idx = tid; idx < 16 * 32; idx += 256) {
            int r = idx >> 5, kk = idx & 31;
            Xt[r][kk] = xsrc[(bb0 + r) * 512 + k0 + kk];
        }
        __syncthreads();
#pragma unroll
        for (int kk = 0; kk < 32; kk++) {
            float wv = Wt[rl][kk];
#pragma unroll
            for (int j = 0; j < 8; j++) acc[j] += wv * Xt[bg * 8 + j][kk];
        }
        __syncthreads();
    }
    const int row = row0 + rl;
    if (ks == 0) {
        const float base = b_ih[row] + b_hh[row];
#pragma unroll
        for (int j = 0; j < 8; j++) {
            int bb = bb0 + bg * 8 + j;
            g_gA[bb * GATES + row] =
                acc[j] + base + W_ih[(size_t)row * INW + g_idx[bb]];
        }
    } else {
#pragma unroll
        for (int j = 0; j < 8; j++) {
            int bb = bb0 + bg * 8 + j;
            g_gB[bb * GATES + row] = acc[j];
        }
    }
}

// ---------------- LSTM pointwise + logits + argmax + q-projection --------
// grid 64 (one block per batch), block 256 (8 warps).
__global__ void finishq_kernel(const float* __restrict__ Wout,
                               const float* __restrict__ b_out,
                               const float* __restrict__ Hc_w,
                               const float* __restrict__ Hc_b,
                               float* __restrict__ out, int t) {
    const int b = blockIdx.x, tid = threadIdx.x;
    const int lane = tid & 31, w = tid >> 5;
    __shared__ __align__(16) float h_s[Hk];
    __shared__ float logit_s[Vk];
#pragma unroll
    for (int r = 0; r < 2; r++) {
        int jj = tid + r * 256;
        float gi = g_gA[b * GATES + jj]        + g_gB[b * GATES + jj];
        float gf = g_gA[b * GATES + 512 + jj]  + g_gB[b * GATES + 512 + jj];
        float gg = g_gA[b * GATES + 1024 + jj] + g_gB[b * GATES + 1024 + jj];
        float go = g_gA[b * GATES + 1536 + jj] + g_gB[b * GATES + 1536 + jj];
        float cprev = g_c[b * Hk + jj];
        float cn = sigmf(gf) * cprev + sigmf(gi) * tanhf(gg);
        float hn = sigmf(go) * tanhf(cn);
        g_c[b * Hk + jj] = cn;
        g_h[b * Hk + jj] = hn;
        h_s[jj] = hn;
    }
    __syncthreads();
    const float4* h4 = (const float4*)h_s;
    const float4 hv0 = h4[lane], hv1 = h4[32 + lane],
                 hv2 = h4[64 + lane], hv3 = h4[96 + lane];
    // logits: warp-dot per vocab entry
#pragma unroll 2
    for (int v = w; v < Vk; v += 8) {
        const float4* wr = (const float4*)(Wout + (size_t)v * Hk);
        float4 w0 = wr[lane], w1 = wr[32 + lane],
               w2 = wr[64 + lane], w3 = wr[96 + lane];
        float s = w0.x * hv0.x + w0.y * hv0.y + w0.z * hv0.z + w0.w * hv0.w
                + w1.x * hv1.x + w1.y * hv1.y + w1.z * hv1.z + w1.w * hv1.w
                + w2.x * hv2.x + w2.y * hv2.y + w2.z * hv2.z + w2.w * hv2.w
                + w3.x * hv3.x + w3.y * hv3.y + w3.z * hv3.z + w3.w * hv3.w;
#pragma unroll
        for (int o = 16; o; o >>= 1) s += __shfl_xor_sync(0xffffffffu, s, o);
        if (lane == 0) {
            float lv = s + b_out[v];
            logit_s[v] = lv;
            out[((size_t)b * Tk + t) * Vk + v] = lv;
        }
    }
    __syncthreads();
    if (tid == 0) {
        float best = logit_s[0];
        int bi = 0;
        for (int v = 1; v < Vk; v++) {
            float lv = logit_s[v];
            if (lv > best) { best = lv; bi = v; }
        }
        g_idx[b] = bi;
    }
    // q = Hc_w @ h + Hc_b : warp w handles rows [w*64, w*64+64), 4 at a time
    for (int g = 0; g < 16; g++) {
        const int r0 = w * 64 + g * 4;
        float s[4];
#pragma unroll
        for (int k = 0; k < 4; k++) {
            const float4* wr = (const float4*)(Hc_w + (size_t)(r0 + k) * Hk);
            float4 w0 = wr[lane], w1 = wr[32 + lane],
                   w2 = wr[64 + lane], w3 = wr[96 + lane];
            s[k] = w0.x * hv0.x + w0.y * hv0.y + w0.z * hv0.z + w0.w * hv0.w
                 + w1.x * hv1.x + w1.y * hv1.y + w1.z * hv1.z + w1.w * hv1.w
                 + w2.x * hv2.x + w2.y * hv2.y + w2.z * hv2.z + w2.w * hv2.w
                 + w3.x * hv3.x + w3.y * hv3.y + w3.z * hv3.z + w3.w * hv3.w;
        }
#pragma unroll
        for (int k = 0; k < 4; k++) {
#pragma unroll
            for (int o = 16; o; o >>= 1)
                s[k] += __shfl_xor_sync(0xffffffffu, s[k], o);
        }
        if (lane < 4) g_q[b * Ak + r0 + lane] = s[lane] + Hc_b[r0 + lane];
    }
}

// ---------------- launch --------------------------------------------------
extern "C" void kernel_launch(void* const* d_in, const int* in_sizes, int n_in,
                              void* d_out, int out_size) {
    const float* image  = (const float*)d_in[0];
    const int*   labels = (const int*)d_in[1];
    const float* Ic_w   = (const float*)d_in[2];
    const float* Ic_b   = (const float*)d_in[3];
    const float* Hc_w   = (const float*)d_in[4];
    const float* Hc_b   = (const float*)d_in[5];
    const float* W_ih   = (const float*)d_in[6];
    const float* b_ih   = (const float*)d_in[7];
    const float* W_hh   = (const float*)d_in[8];
    const float* b_hh   = (const float*)d_in[9];
    const float* Wout   = (const float*)d_in[10];
    const float* b_out  = (const float*)d_in[11];
    float* out = (float*)d_out;

    const int smem_attn = SMEM_ATTN_FLOATS * 4;
    static int attr_done = 0;
    if (!attr_done) {
        cudaFuncSetAttribute(attn_kernel,
                             cudaFuncAttributeMaxDynamicSharedMemorySize,
                             smem_attn);
        attr_done = 1;
    }

    init_kernel<<<Bk, 512>>>(labels, Hc_b);
    keys_gemm<<<dim3((Bk * Sk) / 64, Ak / 64), 256>>>(image, Ic_w, Ic_b);

    for (int t = 0; t < Tk; t++) {
        attn_kernel<<<Bk * NCHUNK, 256, smem_attn>>>();
        gates_kernel<<<128, 256>>>(W_ih, b_ih, W_hh, b_hh);
        finishq_kernel<<<Bk, 256>>>(Wout, b_out, Hc_w, Hc_b, out, t);
    }
}

// round 7
// speedup vs baseline: 2.6030x; 1.9361x over previous
#include <cuda_runtime.h>
#include <math.h>

#define Bk 64
#define Sk 1024
#define Ck 512
#define Vk 140
#define Ak 512
#define Hk 512
#define Tk 128
#define GATES 2048   // 4*H
#define INW 652      // V + A
#define NCHUNK 32    // S chunks per batch (32 rows each)
#define KSPLIT 8     // gates K splits

// ---------------- device state (static allocation only) ----------------
__device__ float g_keys[(size_t)Bk * Sk * Ak];     // 134 MB
__device__ float g_h[Bk * Hk];
__device__ float g_c[Bk * Hk];
__device__ float g_q[Bk * Ak];
__device__ float g_ctx[Bk * Ak];
__device__ float g_gp[KSPLIT][Bk * GATES];         // gates partials, 4 MB
__device__ float g_pm[Bk * NCHUNK];
__device__ float g_pl[Bk * NCHUNK];
__device__ float g_pctx[(size_t)Bk * NCHUNK * Ak]; // 4 MB
__device__ float g_logits[Bk * Vk];
__device__ int   g_cnt[Bk];
__device__ int   g_fcnt[Bk];
__device__ int   g_idx[Bk];

__device__ __forceinline__ float sigmf(float x) { return 1.f / (1.f + expf(-x)); }

// ---------------- init ---------------------------------------------------
__global__ void init_kernel(const int* __restrict__ labels,
                            const float* __restrict__ Hc_b) {
    int b = blockIdx.x, tid = threadIdx.x;
    g_h[b * Hk + tid] = 0.f;
    g_c[b * Hk + tid] = 0.f;
    g_q[b * Ak + tid] = Hc_b[tid];
    if (tid == 0) { g_idx[b] = labels[b * Tk]; g_cnt[b] = 0; g_fcnt[b] = 0; }
}

// ---------------- keys = X @ Ic_w^T + Ic_b  (once) ------------------------
__global__ void keys_gemm(const float* __restrict__ X,
                          const float* __restrict__ W,
                          const float* __restrict__ bias) {
    const int bs0 = blockIdx.x * 64;
    const int a0  = blockIdx.y * 64;
    const int tid = threadIdx.x;
    const int tx = tid & 15, ty = tid >> 4;
    __shared__ float Xs[64][33];
    __shared__ float Ws[64][33];
    float acc[4][4] = {};
    for (int k0 = 0; k0 < Ck; k0 += 32) {
        for (int idx = tid; idx < 64 * 32; idx += 256) {
            int r = idx >> 5, kk = idx & 31;
            Xs[r][kk] = X[(size_t)(bs0 + r) * Ck + k0 + kk];
            Ws[r][kk] = W[(size_t)(a0 + r) * Ck + k0 + kk];
        }
        __syncthreads();
#pragma unroll
        for (int kk = 0; kk < 32; kk++) {
            float xr[4], wc[4];
#pragma unroll
            for (int i = 0; i < 4; i++) xr[i] = Xs[ty * 4 + i][kk];
#pragma unroll
            for (int j = 0; j < 4; j++) wc[j] = Ws[tx * 4 + j][kk];
#pragma unroll
            for (int i = 0; i < 4; i++)
#pragma unroll
                for (int j = 0; j < 4; j++) acc[i][j] += xr[i] * wc[j];
        }
        __syncthreads();
    }
#pragma unroll
    for (int i = 0; i < 4; i++)
#pragma unroll
        for (int j = 0; j < 4; j++)
            g_keys[(size_t)(bs0 + ty * 4 + i) * Ak + a0 + tx * 4 + j] =
                acc[i][j] + bias[a0 + tx * 4 + j];
}

// ---------------- attention: two-pass block softmax + fused merge --------
// grid 2048 (64 b x 32 chunks of 32 s), block 256 (8 warps, 4 rows/warp).
#define SMEM_ATTN_FLOATS (16384 + 512 + 512 + 32 + 32 + 8)
__global__ void attn_kernel() {
    extern __shared__ float sm[];
    float* keys_s = sm;                 // [32][512]
    float* q_s    = sm + 16384;         // [512]
    float* ctx_s  = sm + 16896;         // [512]
    float* scores = sm + 17408;         // [32]
    float* facs   = sm + 17440;         // [32]
    float* lg_s   = sm + 17472;         // [1]
    int*   flag   = (int*)(sm + 17473); // [1]

    const int bx = blockIdx.x;
    const int b = bx >> 5;
    const int chunk = bx & 31;
    const int tid = threadIdx.x;
    const int lane = tid & 31;
    const int w = tid >> 5;

    q_s[tid]       = g_q[b * Ak + tid];
    q_s[tid + 256] = g_q[b * Ak + tid + 256];
    ctx_s[tid] = 0.f;
    ctx_s[tid + 256] = 0.f;
    __syncthreads();

    const float4* q4 = (const float4*)q_s;
    const float4 qv0 = q4[lane], qv1 = q4[32 + lane],
                 qv2 = q4[64 + lane], qv3 = q4[96 + lane];

    // ---- Pass A: load rows to smem, compute raw scores
    const float* kb = g_keys + ((size_t)b * Sk + chunk * 32) * Ak;
#pragma unroll
    for (int i = 0; i < 4; i++) {
        const int row = w * 4 + i;
        const float4* src = (const float4*)(kb + (size_t)row * Ak);
        float4 k0 = src[lane], k1 = src[32 + lane],
               k2 = src[64 + lane], k3 = src[96 + lane];
        float4* dst = (float4*)(keys_s + row * Ak);
        dst[lane] = k0; dst[32 + lane] = k1;
        dst[64 + lane] = k2; dst[96 + lane] = k3;
        float d = k0.x * qv0.x + k0.y * qv0.y + k0.z * qv0.z + k0.w * qv0.w
                + k1.x * qv1.x + k1.y * qv1.y + k1.z * qv1.z + k1.w * qv1.w
                + k2.x * qv2.x + k2.y * qv2.y + k2.z * qv2.z + k2.w * qv2.w
                + k3.x * qv3.x + k3.y * qv3.y + k3.z * qv3.z + k3.w * qv3.w;
#pragma unroll
        for (int o = 16; o; o >>= 1) d += __shfl_xor_sync(0xffffffffu, d, o);
        if (lane == 0) scores[row] = d * 0.04419417382415922f;  // 1/sqrt(512)
    }
    __syncthreads();

    // ---- Pass B: exact block softmax stats
    float s_l = scores[lane];
    float M = s_l;
#pragma unroll
    for (int o = 16; o; o >>= 1) M = fmaxf(M, __shfl_xor_sync(0xffffffffu, M, o));
    float p_l = expf(s_l - M);
    float L = p_l;
#pragma unroll
    for (int o = 16; o; o >>= 1) L += __shfl_xor_sync(0xffffffffu, L, o);

    // ---- Pass C: weighted sum from smem
    float4 a0 = make_float4(0, 0, 0, 0), a1 = a0, a2 = a0, a3 = a0;
#pragma unroll
    for (int i = 0; i < 4; i++) {
        const int row = w * 4 + i;
        const float p = __shfl_sync(0xffffffffu, p_l, row);
        const float4* kr = (const float4*)(keys_s + row * Ak);
        float4 k0 = kr[lane], k1 = kr[32 + lane],
               k2 = kr[64 + lane], k3 = kr[96 + lane];
        a0.x += p * k0.x; a0.y += p * k0.y; a0.z += p * k0.z; a0.w += p * k0.w;
        a1.x += p * k1.x; a1.y += p * k1.y; a1.z += p * k1.z; a1.w += p * k1.w;
        a2.x += p * k2.x; a2.y += p * k2.y; a2.z += p * k2.z; a2.w += p * k2.w;
        a3.x += p * k3.x; a3.y += p * k3.y; a3.z += p * k3.z; a3.w += p * k3.w;
    }

    // deterministic 8-round cross-warp accumulation into ctx_s
    for (int r = 0; r < 8; r++) {
        if (w == r) {
            float* c0 = ctx_s + lane * 4;
            c0[0]   += a0.x; c0[1]   += a0.y; c0[2]   += a0.z; c0[3]   += a0.w;
            c0[128] += a1.x; c0[129] += a1.y; c0[130] += a1.z; c0[131] += a1.w;
            c0[256] += a2.x; c0[257] += a2.y; c0[258] += a2.z; c0[259] += a2.w;
            c0[384] += a3.x; c0[385] += a3.y; c0[386] += a3.z; c0[387] += a3.w;
        }
        __syncthreads();
    }

    g_pctx[(size_t)bx * Ak + tid]       = ctx_s[tid];
    g_pctx[(size_t)bx * Ak + tid + 256] = ctx_s[tid + 256];
    if (tid == 0) { g_pm[bx] = M; g_pl[bx] = L; }

    // ---- fused merge: last block for this batch reduces all 32 partials
    __threadfence();
    if (tid == 0) {
        int prev = atomicAdd(&g_cnt[b], 1);
        flag[0] = (prev == NCHUNK - 1) ? 1 : 0;
    }
    __syncthreads();
    if (flag[0]) {
        __threadfence();
        if (w == 0) {
            float pm_l = __ldcg(&g_pm[b * NCHUNK + lane]);
            float pl_l = __ldcg(&g_pl[b * NCHUNK + lane]);
            float Mg = pm_l;
#pragma unroll
            for (int o = 16; o; o >>= 1)
                Mg = fmaxf(Mg, __shfl_xor_sync(0xffffffffu, Mg, o));
            float fl = expf(pm_l - Mg);
            float Ll = fl * pl_l;
#pragma unroll
            for (int o = 16; o; o >>= 1) Ll += __shfl_xor_sync(0xffffffffu, Ll, o);
            facs[lane] = fl;
            if (lane == 0) lg_s[0] = Ll;
        }
        __syncthreads();
        const float invL = 1.f / lg_s[0];
#pragma unroll
        for (int r2 = 0; r2 < 2; r2++) {
            int a = tid + r2 * 256;
            float s = 0.f;
#pragma unroll
            for (int c = 0; c < NCHUNK; c++)
                s += facs[c] * __ldcg(&g_pctx[(size_t)(b * NCHUNK + c) * Ak + a]);
            g_ctx[b * Ak + a] = s * invL;
        }
        if (tid == 0) g_cnt[b] = 0;
    }
}

// ---------------- gates: 256 blocks, split-K x8, 4x4 register tiles ------
// grid 256 = 32 rowTiles(64 rows) x 8 ksplits(128 K). block 256 = 16x16.
// Each thread: 4 rows x 4 batches. 8 LDS per 16 FMA.
__global__ void gates_kernel(const float* __restrict__ W_ih,
                             const float* __restrict__ b_ih,
                             const float* __restrict__ W_hh,
                             const float* __restrict__ b_hh) {
    const int ks = blockIdx.x & 7;
    const int rowTile = blockIdx.x >> 3;
    const int tid = threadIdx.x;
    const int tx = tid & 15;   // batch group (4 batches)
    const int ty = tid >> 4;   // row group (4 rows)
    __shared__ float Wt[64][33];
    __shared__ float Xt[64][33];
    float acc[4][4] = {};
    const int row0 = rowTile * 64;
    const int kbase = ks * 128;
    for (int k0 = 0; k0 < 128; k0 += 32) {
        for (int idx = tid; idx < 64 * 32; idx += 256) {
            int r = idx >> 5, kk = idx & 31;
            int kg = kbase + k0 + kk;
            int row = row0 + r;
            Wt[r][kk] = (kg < 512) ? W_ih[(size_t)row * INW + Vk + kg]
                                   : W_hh[(size_t)row * Hk + kg - 512];
        }
        for (int idx = tid; idx < 64 * 32; idx += 256) {
            int r = idx >> 5, kk = idx & 31;
            int kg = kbase + k0 + kk;
            Xt[r][kk] = (kg < 512) ? g_ctx[r * Ak + kg]
                                   : g_h[r * Hk + kg - 512];
        }
        __syncthreads();
#pragma unroll
        for (int kk = 0; kk < 32; kk++) {
            float wv[4], xv[4];
#pragma unroll
            for (int i = 0; i < 4; i++) wv[i] = Wt[ty * 4 + i][kk];
#pragma unroll
            for (int j = 0; j < 4; j++) xv[j] = Xt[tx * 4 + j][kk];
#pragma unroll
            for (int i = 0; i < 4; i++)
#pragma unroll
                for (int j = 0; j < 4; j++) acc[i][j] += wv[i] * xv[j];
        }
        __syncthreads();
    }
#pragma unroll
    for (int i = 0; i < 4; i++) {
        const int row = row0 + ty * 4 + i;
        float extra = 0.f;
        if (ks == 0) extra = b_ih[row] + b_hh[row];
#pragma unroll
        for (int j = 0; j < 4; j++) {
            const int bb = tx * 4 + j;
            float v = acc[i][j] + extra;
            if (ks == 0) v += W_ih[(size_t)row * INW + g_idx[bb]];
            g_gp[ks][bb * GATES + row] = v;
        }
    }
}

// ---------------- finish: pointwise + logits + argmax + qproj ------------
// grid 256 = 64 batches x 4 slices, block 256 (8 warps).
// Every slice recomputes the full pointwise (h in smem); slice owns 35
// logit rows + 128 q rows; last-arriving slice does the argmax.
__global__ void finishq_kernel(const float* __restrict__ Wout,
                               const float* __restrict__ b_out,
                               const float* __restrict__ Hc_w,
                               const float* __restrict__ Hc_b,
                               float* __restrict__ out, int t) {
    const int b = blockIdx.x >> 2;
    const int slice = blockIdx.x & 3;
    const int tid = threadIdx.x;
    const int lane = tid & 31, w = tid >> 5;
    __shared__ __align__(16) float h_s[Hk];
    __shared__ int flag_s[1];

#pragma unroll
    for (int r = 0; r < 2; r++) {
        int jj = tid + r * 256;
        float gi = 0.f, gf = 0.f, gg = 0.f, go = 0.f;
#pragma unroll
        for (int p = 0; p < KSPLIT; p++) {
            const float* gp = g_gp[p] + b * GATES;
            gi += gp[jj];
            gf += gp[512 + jj];
            gg += gp[1024 + jj];
            go += gp[1536 + jj];
        }
        float cprev = g_c[b * Hk + jj];
        float cn = sigmf(gf) * cprev + sigmf(gi) * tanhf(gg);
        float hn = sigmf(go) * tanhf(cn);
        if (slice == 0) { g_c[b * Hk + jj] = cn; g_h[b * Hk + jj] = hn; }
        h_s[jj] = hn;
    }
    __syncthreads();
    const float4* h4 = (const float4*)h_s;
    const float4 hv0 = h4[lane], hv1 = h4[32 + lane],
                 hv2 = h4[64 + lane], hv3 = h4[96 + lane];

    // logits: rows [slice*35, slice*35+35)
    for (int vi = w; vi < 35; vi += 8) {
        const int v = slice * 35 + vi;
        const float4* wr = (const float4*)(Wout + (size_t)v * Hk);
        float4 w0 = wr[lane], w1 = wr[32 + lane],
               w2 = wr[64 + lane], w3 = wr[96 + lane];
        float s = w0.x * hv0.x + w0.y * hv0.y + w0.z * hv0.z + w0.w * hv0.w
                + w1.x * hv1.x + w1.y * hv1.y + w1.z * hv1.z + w1.w * hv1.w
                + w2.x * hv2.x + w2.y * hv2.y + w2.z * hv2.z + w2.w * hv2.w
                + w3.x * hv3.x + w3.y * hv3.y + w3.z * hv3.z + w3.w * hv3.w;
#pragma unroll
        for (int o = 16; o; o >>= 1) s += __shfl_xor_sync(0xffffffffu, s, o);
        if (lane == 0) {
            float lv = s + b_out[v];
            g_logits[b * Vk + v] = lv;
            out[((size_t)b * Tk + t) * Vk + v] = lv;
        }
    }

    // qproj: rows [slice*128, slice*128+128), warp w owns 16 rows, 4 at a time
#pragma unroll
    for (int g = 0; g < 4; g++) {
        const int r0 = slice * 128 + w * 16 + g * 4;
        float s[4];
#pragma unroll
        for (int k = 0; k < 4; k++) {
            const float4* wr = (const float4*)(Hc_w + (size_t)(r0 + k) * Hk);
            float4 w0 = wr[lane], w1 = wr[32 + lane],
                   w2 = wr[64 + lane], w3 = wr[96 + lane];
            s[k] = w0.x * hv0.x + w0.y * hv0.y + w0.z * hv0.z + w0.w * hv0.w
                 + w1.x * hv1.x + w1.y * hv1.y + w1.z * hv1.z + w1.w * hv1.w
                 + w2.x * hv2.x + w2.y * hv2.y + w2.z * hv2.z + w2.w * hv2.w
                 + w3.x * hv3.x + w3.y * hv3.y + w3.z * hv3.z + w3.w * hv3.w;
        }
#pragma unroll
        for (int k = 0; k < 4; k++) {
#pragma unroll
            for (int o = 16; o; o >>= 1)
                s[k] += __shfl_xor_sync(0xffffffffu, s[k], o);
        }
        if (lane < 4) g_q[b * Ak + r0 + lane] = s[lane] + Hc_b[r0 + lane];
    }

    // argmax: last slice for this batch does it
    __threadfence();
    if (tid == 0) {
        int prev = atomicAdd(&g_fcnt[b], 1);
        flag_s[0] = (prev == 3) ? 1 : 0;
    }
    __syncthreads();
    if (flag_s[0] && tid == 0) {
        __threadfence();
        float best = __ldcg(&g_logits[b * Vk]);
        int bi = 0;
        for (int v = 1; v < Vk; v++) {
            float lv = __ldcg(&g_logits[b * Vk + v]);
            if (lv > best) { best = lv; bi = v; }
        }
        g_idx[b] = bi;
        g_fcnt[b] = 0;
    }
}

// ---------------- launch --------------------------------------------------
extern "C" void kernel_launch(void* const* d_in, const int* in_sizes, int n_in,
                              void* d_out, int out_size) {
    const float* image  = (const float*)d_in[0];
    const int*   labels = (const int*)d_in[1];
    const float* Ic_w   = (const float*)d_in[2];
    const float* Ic_b   = (const float*)d_in[3];
    const float* Hc_w   = (const float*)d_in[4];
    const float* Hc_b   = (const float*)d_in[5];
    const float* W_ih   = (const float*)d_in[6];
    const float* b_ih   = (const float*)d_in[7];
    const float* W_hh   = (const float*)d_in[8];
    const float* b_hh   = (const float*)d_in[9];
    const float* Wout   = (const float*)d_in[10];
    const float* b_out  = (const float*)d_in[11];
    float* out = (float*)d_out;

    const int smem_attn = SMEM_ATTN_FLOATS * 4;
    cudaFuncSetAttribute(attn_kernel,
                         cudaFuncAttributeMaxDynamicSharedMemorySize,
                         smem_attn);

    init_kernel<<<Bk, 512>>>(labels, Hc_b);
    keys_gemm<<<dim3((Bk * Sk) / 64, Ak / 64), 256>>>(image, Ic_w, Ic_b);

    for (int t = 0; t < Tk; t++) {
        attn_kernel<<<Bk * NCHUNK, 256, smem_attn>>>();
        gates_kernel<<<256, 256>>>(W_ih, b_ih, W_hh, b_hh);
        finishq_kernel<<<256, 256>>>(Wout, b_out, Hc_w, Hc_b, out, t);
    }
}

// round 9
// speedup vs baseline: 2.8418x; 1.0917x over previous
#include <cuda_runtime.h>
#include <math.h>

#define Bk 64
#define Sk 1024
#define Ck 512
#define Vk 140
#define Ak 512
#define Hk 512
#define Tk 128
#define GATES 2048   // 4*H
#define INW 652      // V + A
#define NCHUNK 32    // S chunks per batch (32 rows each)
#define KSPLIT 8     // gates K splits
#define NBLK 148     // persistent grid: <= SM count, 1 block/SM (smem-limited)
#define NVB  296     // 2 virtual blocks per block
#define VSMF 17472   // floats of smem per virtual block

// ---------------- device state (static allocation only) ----------------
__device__ float g_keys[(size_t)Bk * Sk * Ak];     // 134 MB
__device__ float g_h[Bk * Hk];
__device__ float g_c[2][Bk * Hk];                  // parity double buffer
__device__ float g_q[Bk * Ak];
__device__ float g_ctx[Bk * Ak];
__device__ float g_gp[KSPLIT][Bk * GATES];         // gates partials
__device__ float g_pm[Bk * NCHUNK];
__device__ float g_pl[Bk * NCHUNK];
__device__ float g_pctx[(size_t)Bk * NCHUNK * Ak];
__device__ float g_logits[Bk * Vk];
__device__ int   g_idx[Bk];
__device__ int           g_bar_cnt;
__device__ volatile int  g_bar_gen;

__device__ __forceinline__ float sigmf(float x) { return 1.f / (1.f + expf(-x)); }

// virtual-block barrier: 256 threads, named barrier id 1 or 2
__device__ __forceinline__ void vb_sync(int sb) {
    asm volatile("bar.sync %0, 256;" :: "r"(sb) : "memory");
}

// grid-wide barrier (all NBLK blocks resident by construction:
// grid <= SM count and smem caps occupancy at 1 block/SM)
__device__ __forceinline__ void grid_sync() {
    __syncthreads();
    if (threadIdx.x == 0) {
        __threadfence();
        int gen = g_bar_gen;                 // read BEFORE arrive
        int prev = atomicAdd(&g_bar_cnt, 1);
        if (prev == NBLK - 1) {
            g_bar_cnt = 0;
            __threadfence();
            g_bar_gen = gen + 1;
        } else {
            while (g_bar_gen == gen) { __nanosleep(32); }
        }
        __threadfence();
    }
    __syncthreads();
}

// ---------------- init ---------------------------------------------------
__global__ void init_kernel(const int* __restrict__ labels,
                            const float* __restrict__ Hc_b) {
    int b = blockIdx.x, tid = threadIdx.x;
    g_h[b * Hk + tid] = 0.f;
    g_c[0][b * Hk + tid] = 0.f;
    g_q[b * Ak + tid] = Hc_b[tid];
    if (tid == 0) g_idx[b] = labels[b * Tk];
}

// ---------------- keys = X @ Ic_w^T + Ic_b  (once) ------------------------
__global__ void keys_gemm(const float* __restrict__ X,
                          const float* __restrict__ W,
                          const float* __restrict__ bias) {
    const int bs0 = blockIdx.x * 64;
    const int a0  = blockIdx.y * 64;
    const int tid = threadIdx.x;
    const int tx = tid & 15, ty = tid >> 4;
    __shared__ float Xs[64][33];
    __shared__ float Ws[64][33];
    float acc[4][4] = {};
    for (int k0 = 0; k0 < Ck; k0 += 32) {
        for (int idx = tid; idx < 64 * 32; idx += 256) {
            int r = idx >> 5, kk = idx & 31;
            Xs[r][kk] = X[(size_t)(bs0 + r) * Ck + k0 + kk];
            Ws[r][kk] = W[(size_t)(a0 + r) * Ck + k0 + kk];
        }
        __syncthreads();
#pragma unroll
        for (int kk = 0; kk < 32; kk++) {
            float xr[4], wc[4];
#pragma unroll
            for (int i = 0; i < 4; i++) xr[i] = Xs[ty * 4 + i][kk];
#pragma unroll
            for (int j = 0; j < 4; j++) wc[j] = Ws[tx * 4 + j][kk];
#pragma unroll
            for (int i = 0; i < 4; i++)
#pragma unroll
                for (int j = 0; j < 4; j++) acc[i][j] += xr[i] * wc[j];
        }
        __syncthreads();
    }
#pragma unroll
    for (int i = 0; i < 4; i++)
#pragma unroll
        for (int j = 0; j < 4; j++)
            g_keys[(size_t)(bs0 + ty * 4 + i) * Ak + a0 + tx * 4 + j] =
                acc[i][j] + bias[a0 + tx * 4 + j];
}

// ---------------- persistent mega kernel ----------------------------------
__global__ __launch_bounds__(512, 1)
void mega_kernel(const float* __restrict__ W_ih, const float* __restrict__ b_ih,
                 const float* __restrict__ W_hh, const float* __restrict__ b_hh,
                 const float* __restrict__ Wout, const float* __restrict__ b_out,
                 const float* __restrict__ Hc_w, const float* __restrict__ Hc_b,
                 float* __restrict__ out) {
    extern __shared__ float smraw[];
    const int hb   = threadIdx.x >> 8;   // which virtual block (0/1)
    const int tid  = threadIdx.x & 255;  // tid within virtual block
    const int sb   = hb + 1;             // named barrier id
    float* vsm = smraw + hb * VSMF;
    const int vb = blockIdx.x * 2 + hb;  // 0..295
    const int lane = tid & 31;
    const int w = tid >> 5;

    for (int t = 0; t < Tk; t++) {
        // ================= Phase A: attention partials ====================
        {
            float* keys_s = vsm;            // [32][512]
            float* q_s    = vsm + 16384;    // [512]
            float* ctx_s  = vsm + 16896;    // [512]
            float* scores = vsm + 17408;    // [32]
            for (int task = vb; task < Bk * NCHUNK; task += NVB) {
                const int b = task >> 5, chunk = task & 31;
                q_s[tid]       = __ldcg(&g_q[b * Ak + tid]);
                q_s[tid + 256] = __ldcg(&g_q[b * Ak + tid + 256]);
                ctx_s[tid] = 0.f;
                ctx_s[tid + 256] = 0.f;
                vb_sync(sb);
                const float4* q4 = (const float4*)q_s;
                const float4 qv0 = q4[lane], qv1 = q4[32 + lane],
                             qv2 = q4[64 + lane], qv3 = q4[96 + lane];
                const float* kb = g_keys + ((size_t)b * Sk + chunk * 32) * Ak;
#pragma unroll
                for (int i = 0; i < 4; i++) {
                    const int row = w * 4 + i;
                    const float4* src = (const float4*)(kb + (size_t)row * Ak);
                    float4 k0 = src[lane], k1 = src[32 + lane],
                           k2 = src[64 + lane], k3 = src[96 + lane];
                    float4* dst = (float4*)(keys_s + row * Ak);
                    dst[lane] = k0; dst[32 + lane] = k1;
                    dst[64 + lane] = k2; dst[96 + lane] = k3;
                    float d = k0.x*qv0.x + k0.y*qv0.y + k0.z*qv0.z + k0.w*qv0.w
                            + k1.x*qv1.x + k1.y*qv1.y + k1.z*qv1.z + k1.w*qv1.w
                            + k2.x*qv2.x + k2.y*qv2.y + k2.z*qv2.z + k2.w*qv2.w
                            + k3.x*qv3.x + k3.y*qv3.y + k3.z*qv3.z + k3.w*qv3.w;
#pragma unroll
                    for (int o = 16; o; o >>= 1)
                        d += __shfl_xor_sync(0xffffffffu, d, o);
                    if (lane == 0) scores[row] = d * 0.04419417382415922f;
                }
                vb_sync(sb);
                // block softmax stats (redundant per warp)
                float s_l = scores[lane];
                float M = s_l;
#pragma unroll
                for (int o = 16; o; o >>= 1)
                    M = fmaxf(M, __shfl_xor_sync(0xffffffffu, M, o));
                float p_l = expf(s_l - M);
                float L = p_l;
#pragma unroll
                for (int o = 16; o; o >>= 1)
                    L += __shfl_xor_sync(0xffffffffu, L, o);
                // weighted sum from smem
                float4 a0 = make_float4(0,0,0,0), a1 = a0, a2 = a0, a3 = a0;
#pragma unroll
                for (int i = 0; i < 4; i++) {
                    const int row = w * 4 + i;
                    const float p = __shfl_sync(0xffffffffu, p_l, row);
                    const float4* kr = (const float4*)(keys_s + row * Ak);
                    float4 k0 = kr[lane], k1 = kr[32 + lane],
                           k2 = kr[64 + lane], k3 = kr[96 + lane];
                    a0.x += p*k0.x; a0.y += p*k0.y; a0.z += p*k0.z; a0.w += p*k0.w;
                    a1.x += p*k1.x; a1.y += p*k1.y; a1.z += p*k1.z; a1.w += p*k1.w;
                    a2.x += p*k2.x; a2.y += p*k2.y; a2.z += p*k2.z; a2.w += p*k2.w;
                    a3.x += p*k3.x; a3.y += p*k3.y; a3.z += p*k3.z; a3.w += p*k3.w;
                }
                // deterministic 8-round cross-warp accumulation
                for (int r = 0; r < 8; r++) {
                    if (w == r) {
                        float* c0 = ctx_s + lane * 4;
                        c0[0]   += a0.x; c0[1]   += a0.y; c0[2]   += a0.z; c0[3]   += a0.w;
                        c0[128] += a1.x; c0[129] += a1.y; c0[130] += a1.z; c0[131] += a1.w;
                        c0[256] += a2.x; c0[257] += a2.y; c0[258] += a2.z; c0[259] += a2.w;
                        c0[384] += a3.x; c0[385] += a3.y; c0[386] += a3.z; c0[387] += a3.w;
                    }
                    vb_sync(sb);
                }
                __stcg(&g_pctx[(size_t)task * Ak + tid],       ctx_s[tid]);
                __stcg(&g_pctx[(size_t)task * Ak + tid + 256], ctx_s[tid + 256]);
                if (tid == 0) { __stcg(&g_pm[task], M); __stcg(&g_pl[task], L); }
            }
        }
        grid_sync();

        // ========== Phase M: merge partials; argmax of prev logits ========
        if (vb < 64) {
            const int b = vb;
            float* facs = vsm + 17408;  // [32]
            float* lg   = vsm + 17440;  // [1]
            if (w == 0) {
                float pm_l = __ldcg(&g_pm[b * NCHUNK + lane]);
                float pl_l = __ldcg(&g_pl[b * NCHUNK + lane]);
                float Mg = pm_l;
#pragma unroll
                for (int o = 16; o; o >>= 1)
                    Mg = fmaxf(Mg, __shfl_xor_sync(0xffffffffu, Mg, o));
                float fl = expf(pm_l - Mg);
                float Ll = fl * pl_l;
#pragma unroll
                for (int o = 16; o; o >>= 1)
                    Ll += __shfl_xor_sync(0xffffffffu, Ll, o);
                facs[lane] = fl;
                if (lane == 0) lg[0] = Ll;
            }
            vb_sync(sb);
            const float invL = 1.f / lg[0];
#pragma unroll
            for (int r2 = 0; r2 < 2; r2++) {
                int a = tid + r2 * 256;
                float s = 0.f;
#pragma unroll
                for (int c = 0; c < NCHUNK; c++)
                    s += facs[c] *
                         __ldcg(&g_pctx[(size_t)(b * NCHUNK + c) * Ak + a]);
                __stcg(&g_ctx[b * Ak + a], s * invL);
            }
        } else if (vb < 128 && t > 0) {
            // argmax of step t-1 logits (first-occurrence semantics)
            const int b = vb - 64;
            if (tid < 32) {
                float best = -1e30f; int bi = 0;
                for (int v = lane; v < Vk; v += 32) {
                    float lv = __ldcg(&g_logits[b * Vk + v]);
                    if (lv > best) { best = lv; bi = v; }
                }
#pragma unroll
                for (int o = 16; o; o >>= 1) {
                    float ov = __shfl_xor_sync(0xffffffffu, best, o);
                    int   oi = __shfl_xor_sync(0xffffffffu, bi,  o);
                    if (ov > best || (ov == best && oi < bi)) { best = ov; bi = oi; }
                }
                if (lane == 0) __stcg(&g_idx[b], bi);
            }
        }
        grid_sync();

        // ================= Phase G: gates (split-K x8) ====================
        if (vb < 256) {
            const int ks = vb & 7;
            const int rowTile = vb >> 3;
            const int tx = tid & 15;   // batch group
            const int ty = tid >> 4;   // row group
            float* Wt = vsm;           // [64][33]
            float* Xt = vsm + 2112;    // [64][33]
            float acc[4][4] = {};
            const int row0 = rowTile * 64;
            const int kbase = ks * 128;
            for (int k0 = 0; k0 < 128; k0 += 32) {
                for (int idx = tid; idx < 64 * 32; idx += 256) {
                    int r = idx >> 5, kk = idx & 31;
                    int kg = kbase + k0 + kk;
                    int row = row0 + r;
                    Wt[r * 33 + kk] = (kg < 512)
                        ? W_ih[(size_t)row * INW + Vk + kg]
                        : W_hh[(size_t)row * Hk + kg - 512];
                }
                for (int idx = tid; idx < 64 * 32; idx += 256) {
                    int r = idx >> 5, kk = idx & 31;
                    int kg = kbase + k0 + kk;
                    Xt[r * 33 + kk] = (kg < 512)
                        ? __ldcg(&g_ctx[r * Ak + kg])
                        : __ldcg(&g_h[r * Hk + kg - 512]);
                }
                vb_sync(sb);
#pragma unroll
                for (int kk = 0; kk < 32; kk++) {
                    float wv[4], xv[4];
#pragma unroll
                    for (int i = 0; i < 4; i++) wv[i] = Wt[(ty * 4 + i) * 33 + kk];
#pragma unroll
                    for (int j = 0; j < 4; j++) xv[j] = Xt[(tx * 4 + j) * 33 + kk];
#pragma unroll
                    for (int i = 0; i < 4; i++)
#pragma unroll
                        for (int j = 0; j < 4; j++) acc[i][j] += wv[i] * xv[j];
                }
                vb_sync(sb);
            }
#pragma unroll
            for (int i = 0; i < 4; i++) {
                const int row = row0 + ty * 4 + i;
                float extra = 0.f;
                if (ks == 0) extra = b_ih[row] + b_hh[row];
#pragma unroll
                for (int j = 0; j < 4; j++) {
                    const int bb = tx * 4 + j;
                    float v = acc[i][j] + extra;
                    if (ks == 0)
                        v += W_ih[(size_t)row * INW + __ldcg(&g_idx[bb])];
                    __stcg(&g_gp[ks][bb * GATES + row], v);
                }
            }
        }
        grid_sync();

        // ========= Phase F: pointwise + logits + qproj (4 slices/b) =======
        if (vb < 256) {
            const int b = vb >> 2;
            const int slice = vb & 3;
            const int p = t & 1;
            float* h_s = vsm;  // [512]
#pragma unroll
            for (int r = 0; r < 2; r++) {
                int jj = tid + r * 256;
                float gi = 0.f, gf = 0.f, gg = 0.f, go = 0.f;
#pragma unroll
                for (int pp = 0; pp < KSPLIT; pp++) {
                    const float* gp = g_gp[pp] + b * GATES;
                    gi += __ldcg(&gp[jj]);
                    gf += __ldcg(&gp[512 + jj]);
                    gg += __ldcg(&gp[1024 + jj]);
                    go += __ldcg(&gp[1536 + jj]);
                }
                float cprev = __ldcg(&g_c[p][b * Hk + jj]);
                float cn = sigmf(gf) * cprev + sigmf(gi) * tanhf(gg);
                float hn = sigmf(go) * tanhf(cn);
                if (slice == 0) {
                    __stcg(&g_c[1 - p][b * Hk + jj], cn);
                    __stcg(&g_h[b * Hk + jj], hn);
                }
                h_s[jj] = hn;
            }
            vb_sync(sb);
            const float4* h4 = (const float4*)h_s;
            const float4 hv0 = h4[lane], hv1 = h4[32 + lane],
                         hv2 = h4[64 + lane], hv3 = h4[96 + lane];
            // logits rows [slice*35, slice*35+35)
            for (int vi = w; vi < 35; vi += 8) {
                const int v = slice * 35 + vi;
                const float4* wr = (const float4*)(Wout + (size_t)v * Hk);
                float4 w0 = wr[lane], w1 = wr[32 + lane],
                       w2 = wr[64 + lane], w3 = wr[96 + lane];
                float s = w0.x*hv0.x + w0.y*hv0.y + w0.z*hv0.z + w0.w*hv0.w
                        + w1.x*hv1.x + w1.y*hv1.y + w1.z*hv1.z + w1.w*hv1.w
                        + w2.x*hv2.x + w2.y*hv2.y + w2.z*hv2.z + w2.w*hv2.w
                        + w3.x*hv3.x + w3.y*hv3.y + w3.z*hv3.z + w3.w*hv3.w;
#pragma unroll
                for (int o = 16; o; o >>= 1)
                    s += __shfl_xor_sync(0xffffffffu, s, o);
                if (lane == 0) {
                    float lv = s + b_out[v];
                    __stcg(&g_logits[b * Vk + v], lv);
                    out[((size_t)b * Tk + t) * Vk + v] = lv;
                }
            }
            // qproj rows [slice*128, slice*128+128)
#pragma unroll
            for (int g = 0; g < 4; g++) {
                const int r0 = slice * 128 + w * 16 + g * 4;
                float s[4];
#pragma unroll
                for (int k = 0; k < 4; k++) {
                    const float4* wr = (const float4*)(Hc_w + (size_t)(r0 + k) * Hk);
                    float4 w0 = wr[lane], w1 = wr[32 + lane],
                           w2 = wr[64 + lane], w3 = wr[96 + lane];
                    s[k] = w0.x*hv0.x + w0.y*hv0.y + w0.z*hv0.z + w0.w*hv0.w
                         + w1.x*hv1.x + w1.y*hv1.y + w1.z*hv1.z + w1.w*hv1.w
                         + w2.x*hv2.x + w2.y*hv2.y + w2.z*hv2.z + w2.w*hv2.w
                         + w3.x*hv3.x + w3.y*hv3.y + w3.z*hv3.z + w3.w*hv3.w;
                }
#pragma unroll
                for (int k = 0; k < 4; k++) {
#pragma unroll
                    for (int o = 16; o; o >>= 1)
                        s[k] += __shfl_xor_sync(0xffffffffu, s[k], o);
                }
                if (lane < 4)
                    __stcg(&g_q[b * Ak + r0 + lane], s[lane] + Hc_b[r0 + lane]);
            }
        }
        grid_sync();
    }
}

// ---------------- launch --------------------------------------------------
extern "C" void kernel_launch(void* const* d_in, const int* in_sizes, int n_in,
                              void* d_out, int out_size) {
    const float* image  = (const float*)d_in[0];
    const int*   labels = (const int*)d_in[1];
    const float* Ic_w   = (const float*)d_in[2];
    const float* Ic_b   = (const float*)d_in[3];
    const float* Hc_w   = (const float*)d_in[4];
    const float* Hc_b   = (const float*)d_in[5];
    const float* W_ih   = (const float*)d_in[6];
    const float* b_ih   = (const float*)d_in[7];
    const float* W_hh   = (const float*)d_in[8];
    const float* b_hh   = (const float*)d_in[9];
    const float* Wout   = (const float*)d_in[10];
    const float* b_out  = (const float*)d_in[11];
    float* out = (float*)d_out;

    const int smem_mega = 2 * VSMF * 4;  // 139776 bytes -> 1 block/SM
    cudaFuncSetAttribute(mega_kernel,
                         cudaFuncAttributeMaxDynamicSharedMemorySize,
                         smem_mega);

    init_kernel<<<Bk, 512>>>(labels, Hc_b);
    keys_gemm<<<dim3((Bk * Sk) / 64, Ak / 64), 256>>>(image, Ic_w, Ic_b);
    mega_kernel<<<NBLK, 512, smem_mega>>>(W_ih, b_ih, W_hh, b_hh,
                                          Wout, b_out, Hc_w, Hc_b, out);
}